// round 15
// baseline (speedup 1.0000x reference)
#include <cuda_runtime.h>

#define CC 768
#define BB 32
#define LL 4096
#define NH 12
#define HD 64
#define EPSV 1e-5f

typedef unsigned long long ull;

// ---------------- packed fp32x2 helpers (FFMA2 — ptxas won't auto-fuse) ----
__device__ __forceinline__ ull fma2(ull a, ull b, ull c) {
    ull d; asm("fma.rn.f32x2 %0,%1,%2,%3;" : "=l"(d) : "l"(a), "l"(b), "l"(c)); return d;
}
__device__ __forceinline__ ull add2(ull a, ull b) {
    ull d; asm("add.rn.f32x2 %0,%1,%2;" : "=l"(d) : "l"(a), "l"(b)); return d;
}
__device__ __forceinline__ float sum2(ull a) {
    float x, y; asm("mov.b64 {%0,%1},%2;" : "=f"(x), "=f"(y) : "l"(a)); return x + y;
}
__device__ __forceinline__ ull pack2(float x, float y) {
    ull d; asm("mov.b64 %0,{%1,%2};" : "=l"(d) : "f"(x), "f"(y)); return d;
}
__device__ __forceinline__ void unpack2(ull a, float& x, float& y) {
    asm("mov.b64 {%0,%1},%2;" : "=f"(x), "=f"(y) : "l"(a));
}

// ---------------- device scratch (no allocations allowed) ----------------
__device__ float g_poolpart[BB * 32 * CC];   // per-(b,chunk) pool partials
__device__ float g_qspart[12 * BB * CC];     // per-kslice q partials
__device__ float g_WkT[CC * CC];             // Wk transposed
__device__ float g_wg[BB * NH * CC];         // folded key weights * gamma
__device__ float g_A[BB * NH];               // sum_c wg
__device__ float g_B2[BB * NH];              // sum_c w*beta + qs.bk
__device__ float g_accx[BB * CC];            // sum_l p_h(l)*rs_l*x[l,c]
__device__ float g_S0[BB * NH];              // sum_l p
__device__ float g_S1[BB * NH];              // sum_l p*rs*mu
__device__ float2 g_st[BB * LL];             // per-token (rs, rs*mu)

// ---------------- K1: pool partials + LN stats + Wk transpose -------------
// grid (32 chunks, 32 b), 256 threads (8 warps); warp streams 16 tokens.
__global__ void __launch_bounds__(256) k1_pool(const float* __restrict__ x,
                                               const float* __restrict__ Wk) {
    int b = blockIdx.y, chunk = blockIdx.x;
    int warp = threadIdx.x >> 5, lane = threadIdx.x & 31;
    __shared__ ull spool[8][384];                    // 24 KB
    __shared__ float tile[32][33];                   // 4.2 KB (transpose)
    ull pacc[12];
    #pragma unroll
    for (int j = 0; j < 12; j++) pacc[j] = 0ull;

    int l0 = chunk * 128 + warp * 16;
    for (int t = 0; t < 16; t++) {
        const ulonglong2* xp = (const ulonglong2*)x + (size_t)(b * LL + l0 + t) * 192 + lane;
        ull sA = 0ull, sQ = 0ull;
        #pragma unroll
        for (int j = 0; j < 6; j++) {
            ulonglong2 u = xp[32 * j];
            pacc[2 * j]     = add2(pacc[2 * j], u.x);
            pacc[2 * j + 1] = add2(pacc[2 * j + 1], u.y);
            sA = add2(sA, u.x); sA = add2(sA, u.y);
            sQ = fma2(u.x, u.x, sQ); sQ = fma2(u.y, u.y, sQ);
        }
        float s = sum2(sA), sq = sum2(sQ);
        float m = (lane & 16) ? sq : s;
        float o = (lane & 16) ? s : sq;
        m += __shfl_xor_sync(~0u, o, 16);
        m += __shfl_xor_sync(~0u, m, 8);
        m += __shfl_xor_sync(~0u, m, 4);
        m += __shfl_xor_sync(~0u, m, 2);
        m += __shfl_xor_sync(~0u, m, 1);
        float oth = __shfl_xor_sync(~0u, m, 16);
        if (lane == 0) {
            float sv = m, sqv = oth;
            float mm = sv * (1.f / (float)CC);
            float rs = rsqrtf(sqv * (1.f / (float)CC) - mm * mm + EPSV);
            g_st[b * LL + l0 + t] = make_float2(rs, rs * mm);
        }
    }
    // block-reduce pool partials -> per-(b,chunk) partial row (no atomics)
    #pragma unroll
    for (int j = 0; j < 6; j++) {
        ulonglong2 v; v.x = pacc[2 * j]; v.y = pacc[2 * j + 1];
        *(ulonglong2*)&spool[warp][2 * (lane + 32 * j)] = v;
    }
    __syncthreads();
    float* pp = g_poolpart + (size_t)(b * 32 + chunk) * CC;
    for (int u = threadIdx.x; u < 384; u += 256) {
        ull s = spool[0][u];
        #pragma unroll
        for (int w = 1; w < 8; w++) s = add2(s, spool[w][u]);
        float fx, fy; unpack2(s, fx, fy);
        pp[2 * u] = fx;
        pp[2 * u + 1] = fy;
    }
    // Wk transpose: 576 tiles of 32x32
    int id = b * 32 + chunk;
    if (id < 576) {
        int x0 = (id % 24) * 32, y0 = (id / 24) * 32;
        #pragma unroll
        for (int k = 0; k < 4; k++) {
            int r = warp + 8 * k;
            tile[r][lane] = Wk[(size_t)(y0 + r) * CC + x0 + lane];
        }
        __syncthreads();
        #pragma unroll
        for (int k = 0; k < 4; k++) {
            int r = warp + 8 * k;
            g_WkT[(size_t)(x0 + r) * CC + y0 + lane] = tile[lane][r];
        }
    }
}

// ---------------- K2b: q partials = (mean @ Wq), split-K x12 --------------
// grid (12 kslices, 32 b), 768 threads. Also zeroes accx/S0/S1.
__global__ void k2_q(const float* __restrict__ Wq) {
    int ks = blockIdx.x, b = blockIdx.y;
    int c = threadIdx.x;
    __shared__ float mean[64];
    if (c < 64) {
        float s = 0.f;
        #pragma unroll
        for (int ch = 0; ch < 32; ch++)
            s += g_poolpart[(size_t)(b * 32 + ch) * CC + ks * 64 + c];
        mean[c] = s * (1.f / (float)LL);
    }
    if (c >= 64 && c < 128) g_accx[b * CC + ks * 64 + (c - 64)] = 0.f;
    if (ks == 0 && c >= 128 && c < 128 + NH) {
        g_S0[b * NH + (c - 128)] = 0.f;
        g_S1[b * NH + (c - 128)] = 0.f;
    }
    __syncthreads();
    const float* wp = Wq + (size_t)(ks * 64) * CC + c;
    float a0 = 0.f, a1 = 0.f, a2 = 0.f, a3 = 0.f;
    #pragma unroll
    for (int cp = 0; cp < 64; cp += 4) {
        float w0 = wp[(size_t)cp * CC];
        float w1 = wp[(size_t)(cp + 1) * CC];
        float w2 = wp[(size_t)(cp + 2) * CC];
        float w3 = wp[(size_t)(cp + 3) * CC];
        a0 = fmaf(mean[cp], w0, a0);
        a1 = fmaf(mean[cp + 1], w1, a1);
        a2 = fmaf(mean[cp + 2], w2, a2);
        a3 = fmaf(mean[cp + 3], w3, a3);
    }
    g_qspart[(size_t)(ks * BB + b) * CC + c] = a0 + a1 + a2 + a3;
}

// ---------------- K2c: w, wg, A, B2 fused (sums q partials + bq) ----------
__global__ void k2_wf(const float* __restrict__ gamma, const float* __restrict__ beta,
                      const float* __restrict__ bk, const float* __restrict__ bq) {
    int h = blockIdx.x, b = blockIdx.y;
    int c = threadIdx.x;
    int warp = c >> 5, lane = c & 31;
    __shared__ float qs[HD];
    __shared__ float rA[24], rB[24];
    if (c < HD) {
        float s = bq[h * HD + c];
        #pragma unroll
        for (int ks = 0; ks < 12; ks++)
            s += g_qspart[(size_t)(ks * BB + b) * CC + h * HD + c];
        qs[c] = s * 0.125f;                          // scale = 64^-0.5
    }
    __syncthreads();
    const float* wt = g_WkT + (size_t)(h * HD) * CC + c;
    float a0 = 0.f, a1 = 0.f;
    #pragma unroll
    for (int d = 0; d < HD; d += 2) {
        float w0 = wt[(size_t)d * CC];
        float w1 = wt[(size_t)(d + 1) * CC];
        a0 = fmaf(qs[d], w0, a0);
        a1 = fmaf(qs[d + 1], w1, a1);
    }
    float acc = a0 + a1;
    float wgv = acc * gamma[c];
    g_wg[(size_t)(b * NH + h) * CC + c] = wgv;
    float sA = wgv;
    float sB = acc * beta[c] + ((c < HD) ? qs[c] * bk[h * HD + c] : 0.f);
    #pragma unroll
    for (int o = 16; o > 0; o >>= 1) {
        sA += __shfl_xor_sync(~0u, sA, o);
        sB += __shfl_xor_sync(~0u, sB, o);
    }
    if (lane == 0) { rA[warp] = sA; rB[warp] = sB; }
    __syncthreads();
    if (c < 32) {
        float a = (c < 24) ? rA[c] : 0.f;
        float bb = (c < 24) ? rB[c] : 0.f;
        #pragma unroll
        for (int o = 16; o > 0; o >>= 1) {
            a += __shfl_xor_sync(~0u, a, o);
            bb += __shfl_xor_sync(~0u, bb, o);
        }
        if (c == 0) {
            g_A[b * NH + h] = a;
            g_B2[b * NH + h] = bb;
        }
    }
}

// ---------------- K3: logits + exp + IN-REGISTER weighted v-accum ---------
// 2-TOKEN register tile: xr[2][12] (48 regs) + acc[12] (24) ~= 110 regs
// natural -> fits 128-reg budget of __launch_bounds__(256,2) WITHOUT spills,
// giving 2 CTAs/SM (16 warps). Per-warp: 8 groups of 2 tokens.
// Reduction: lanes 0-15 carry token0, 16-31 token1 (5-shfl tree); all
// lanes<16 hold e(t0) so broadcasts are shfl(e,0)/shfl(e,16).
__global__ void __launch_bounds__(256, 2) k3_flash(const float* __restrict__ x) {
    int b = blockIdx.y, chunk = blockIdx.x;
    int warp = threadIdx.x >> 5, lane = threadIdx.x & 31;
    __shared__ __align__(16) float wg[NH * CC];       // 36 KB (aliased later)
    __shared__ float hA[NH], hB[NH];
    __shared__ float p[NH][128];                       // 6 KB
    __shared__ float2 st2[128];                        // (rs, rs*mu)
    for (int i = threadIdx.x; i < NH * CC; i += 256)
        wg[i] = g_wg[(size_t)(b * NH) * CC + i];
    if (threadIdx.x < NH) {
        hA[threadIdx.x] = g_A[b * NH + threadIdx.x];
        hB[threadIdx.x] = g_B2[b * NH + threadIdx.x];
    }
    if (threadIdx.x < 128)
        st2[threadIdx.x] = g_st[b * LL + chunk * 128 + threadIdx.x];
    __syncthreads();

    ull acc[12];
    #pragma unroll
    for (int j = 0; j < 12; j++) acc[j] = 0ull;

    bool hi = lane >= 16;
    int tokoff = hi ? 1 : 0;
    int l0 = chunk * 128 + warp * 16;

    for (int g = 0; g < 8; g++) {
        int lbase = l0 + g * 2;          // global token idx
        int sbase = warp * 16 + g * 2;   // smem token idx within chunk
        ull xr[2][12];
        // batch the 12 LDG.128 (MLP=12)
        #pragma unroll
        for (int t = 0; t < 2; t++) {
            const ulonglong2* xp = (const ulonglong2*)x + (size_t)(b * LL + lbase + t) * 192 + lane;
            #pragma unroll
            for (int j = 0; j < 6; j++) {
                ulonglong2 u = xp[32 * j];
                xr[t][2 * j] = u.x;
                xr[t][2 * j + 1] = u.y;
            }
        }
        float rs0 = st2[sbase + 0].x, rs1 = st2[sbase + 1].x;
        float2 stl = st2[sbase + tokoff];   // lanes 0-15 -> t0, 16-31 -> t1
        float e_prev = 0.f;
        #pragma unroll
        for (int h = 0; h < NH; h++) {
            ull a0 = 0ull, a1 = 0ull;
            #pragma unroll
            for (int j = 0; j < 6; j++) {
                ulonglong2 w2 = *(const ulonglong2*)&wg[h * CC + 4 * (lane + 32 * j)];
                a0 = fma2(xr[0][2 * j], w2.x, a0); a0 = fma2(xr[0][2 * j + 1], w2.y, a0);
                a1 = fma2(xr[1][2 * j], w2.x, a1); a1 = fma2(xr[1][2 * j + 1], w2.y, a1);
            }
            float b0 = sum2(a0), b1 = sum2(a1);
            // 5-shfl tree: lanes 0-15 end with token0 sum, 16-31 token1
            float m = hi ? b1 : b0;
            float o = hi ? b0 : b1;
            m += __shfl_xor_sync(~0u, o, 16);
            m += __shfl_xor_sync(~0u, m, 8);
            m += __shfl_xor_sync(~0u, m, 4);
            m += __shfl_xor_sync(~0u, m, 2);
            m += __shfl_xor_sync(~0u, m, 1);
            // logit = rs*dot - (rs*mu)*A + B; logits tiny -> no max shift
            float e = __expf(stl.x * m - stl.y * hA[h] + hB[h]);
            if ((lane & 15) == h) p[h][sbase + tokoff] = e;  // lane h: t0, lane 16+h: t1
            if ((h & 1) == 0) {
                e_prev = e;
            } else {
                int jj = h >> 1;
                // all lanes<16 hold e(*, t0); lanes>=16 hold e(*, t1)
                float q00 = __shfl_sync(~0u, e_prev, 0);   // p(h-1, t0)
                float q01 = __shfl_sync(~0u, e_prev, 16);  // p(h-1, t1)
                float q10 = __shfl_sync(~0u, e, 0);        // p(h,   t0)
                float q11 = __shfl_sync(~0u, e, 16);       // p(h,   t1)
                // channel position jj of lane l belongs to head 2jj (l<16) or 2jj+1
                float w0 = (hi ? q10 : q00) * rs0;
                float w1 = (hi ? q11 : q01) * rs1;
                ull w0p = pack2(w0, w0), w1p = pack2(w1, w1);
                acc[2 * jj]     = fma2(xr[0][2 * jj], w0p, acc[2 * jj]);
                acc[2 * jj]     = fma2(xr[1][2 * jj], w1p, acc[2 * jj]);
                acc[2 * jj + 1] = fma2(xr[0][2 * jj + 1], w0p, acc[2 * jj + 1]);
                acc[2 * jj + 1] = fma2(xr[1][2 * jj + 1], w1p, acc[2 * jj + 1]);
            }
        }
    }
    __syncthreads();

    // Per-head chunk partial sums S0 = sum p, S1 = sum p*rs*mu
    for (int h = warp; h < NH; h += 8) {
        float s0 = 0.f, s1 = 0.f;
        #pragma unroll
        for (int k = 0; k < 4; k++) {
            float pv = p[h][lane + 32 * k];
            s0 += pv;
            s1 = fmaf(pv, st2[lane + 32 * k].y, s1);
        }
        #pragma unroll
        for (int o = 16; o > 0; o >>= 1) {
            s0 += __shfl_xor_sync(~0u, s0, o);
            s1 += __shfl_xor_sync(~0u, s1, o);
        }
        if (lane == 0) {
            atomicAdd(&g_S0[b * NH + h], s0);
            atomicAdd(&g_S1[b * NH + h], s1);
        }
    }

    // Block-reduce v accumulators through smem (alias wg: done with it) and
    // issue one atomic per channel pair.
    ull* sp = (ull*)wg;                               // 8 warps x 384 ull = 24 KB
    #pragma unroll
    for (int j = 0; j < 6; j++) {
        ulonglong2 v; v.x = acc[2 * j]; v.y = acc[2 * j + 1];
        *(ulonglong2*)&sp[warp * 384 + 2 * (lane + 32 * j)] = v;
    }
    __syncthreads();
    for (int u = threadIdx.x; u < 384; u += 256) {
        ull s = sp[u];
        #pragma unroll
        for (int w = 1; w < 8; w++) s = add2(s, sp[w * 384 + u]);
        float fx, fy; unpack2(s, fx, fy);
        atomicAdd(&g_accx[b * CC + 2 * u], fx);
        atomicAdd(&g_accx[b * CC + 2 * u + 1], fy);
    }
}

// ---------------- K4: finalize out = gamma*(accx - S1)/S0 + beta ----------
__global__ void k4_final(const float* __restrict__ gamma, const float* __restrict__ beta,
                         float* __restrict__ out) {
    int b = blockIdx.x;
    int t = threadIdx.x;   // 192
    __shared__ float s0[NH], s1[NH];
    if (t < NH) { s0[t] = g_S0[b * NH + t]; s1[t] = g_S1[b * NH + t]; }
    __syncthreads();
    int h = t >> 4;
    float4 a = ((const float4*)g_accx)[b * 192 + t];
    float4 g = ((const float4*)gamma)[t];
    float4 be = ((const float4*)beta)[t];
    float inv = 1.f / s0[h];
    float sh = s1[h];
    float4 o;
    o.x = fmaf(g.x, (a.x - sh) * inv, be.x);
    o.y = fmaf(g.y, (a.y - sh) * inv, be.y);
    o.z = fmaf(g.z, (a.z - sh) * inv, be.z);
    o.w = fmaf(g.w, (a.w - sh) * inv, be.w);
    ((float4*)out)[b * 192 + t] = o;
}

// ---------------- launch ----------------
extern "C" void kernel_launch(void* const* d_in, const int* in_sizes, int n_in,
                              void* d_out, int out_size) {
    const float* x     = (const float*)d_in[0];
    const float* gamma = (const float*)d_in[1];
    const float* beta  = (const float*)d_in[2];
    const float* Wq    = (const float*)d_in[3];
    const float* bq    = (const float*)d_in[4];
    const float* Wk    = (const float*)d_in[5];
    const float* bk    = (const float*)d_in[6];
    float* out = (float*)d_out;

    k1_pool<<<dim3(32, 32), 256>>>(x, Wk);
    k2_q<<<dim3(12, 32), 768>>>(Wq);
    k2_wf<<<dim3(12, 32), 768>>>(gamma, beta, bk, bq);
    k3_flash<<<dim3(32, 32), 256>>>(x);
    k4_final<<<32, 192>>>(gamma, beta, out);
}